// round 17
// baseline (speedup 1.0000x reference)
#include <cuda_runtime.h>
#include <cuda_bf16.h>

#define B_ 512
#define S_ 512
#define T_ 128
#define END_ID 1
#define L2E 1.4426950408889634f
#define LN2 0.6931471805599453f
#define NC 8
#define NCTA 64
#define SAST 136   // padded bf16 row stride (conflict-free B-frag LDS + STS)

__device__ float g_diff[B_];
__device__ int g_done = 0;

static __device__ __forceinline__ float ex2(float x) {
    float r; asm("ex2.approx.f32 %0, %1;" : "=f"(r) : "f"(x)); return r;
}
static __device__ __forceinline__ float lg2(float x) {
    float r; asm("lg2.approx.f32 %0, %1;" : "=f"(r) : "f"(x)); return r;
}
static __device__ __forceinline__ unsigned int bpack(float lo, float hi) {
    __nv_bfloat162 h = __floats2bfloat162_rn(lo, hi);
    return *reinterpret_cast<unsigned int*>(&h);
}
static __device__ __forceinline__ float warp_sum(float v) {
#pragma unroll
    for (int o = 16; o; o >>= 1) v += __shfl_xor_sync(0xffffffffu, v, o);
    return v;
}

// D/A/B fragment mapping is the standard m16n8k16 layout (PTX ISA):
//   g = lane>>2, t2 = (lane&3)*2
//   A: a0={A[g][t2],A[g][t2+1]} a1={A[g+8][t2],..} a2={A[g][t2+8],..} a3={A[g+8][t2+8],..}
//   B (col-major): b0={B[t2][g],B[t2+1][g]} b1={B[t2+8][g],B[t2+9][g]}
//   D: d0=D[g][t2] d1=D[g][t2+1] d2=D[g+8][t2] d3=D[g+8][t2+1]
#define MMA(D, A, BB0, BB1)                                                  \
    asm("mma.sync.aligned.m16n8k16.row.col.f32.bf16.bf16.f32 "               \
        "{%0,%1,%2,%3}, {%4,%5,%6,%7}, {%8,%9}, {%0,%1,%2,%3};"              \
        : "+f"((D)[0]), "+f"((D)[1]), "+f"((D)[2]), "+f"((D)[3])             \
        : "r"((A)[0]), "r"((A)[1]), "r"((A)[2]), "r"((A)[3]),                \
          "r"(BB0), "r"(BB1))

// 128 threads (4 warps), 8 chains per CTA stepped together on tensor cores.
// Warp w computes rows [32w,32w+32) via two m16n8k16 tiles; per step:
// D[128x8] = E[128x128] * a[128x8], then per-chain scale by exp2(x) and exact
// 2^-k renorm; bf16 state in smem, f32 accumulate. 64 CTAs x 8 chains = 512.
__global__ void __launch_bounds__(128, 1) crf_kernel(
    const float* __restrict__ x,      // [B,S,T]
    const int*   __restrict__ tags,   // [B,S]
    const float* __restrict__ mask,   // [B,S]
    const float* __restrict__ trans,  // [T,T]
    float* __restrict__ out)
{
    const int tid  = threadIdx.x;
    const int w    = tid >> 5;
    const int lane = tid & 31;
    const int g    = lane >> 2;
    const int t2   = (lane & 3) * 2;
    const int c0   = t2, c1 = t2 + 1;     // chains this thread's D columns own
    const int rA   = w * 32 + g;          // base row (m-tile 0)
    const int base = blockIdx.x * NC;

    __shared__ __align__(16) __nv_bfloat16 sa[2][NC][SAST];
    __shared__ float s_red[4];
    __shared__ int   s_len[NC];
    __shared__ int   s_K[NC];
    __shared__ int   s_last;

    // ---- E fragments: 2 m-tiles x 8 k-tiles x 4 regs = exp(trans) in bf16 ----
    unsigned int ea[2][8][4];
#pragma unroll
    for (int mt = 0; mt < 2; mt++) {
        const int r0 = w * 32 + mt * 16 + g;
        const float* tr0 = trans + r0 * T_;
        const float* tr1 = trans + (r0 + 8) * T_;
#pragma unroll
        for (int kt = 0; kt < 8; kt++) {
            int cb = kt * 16 + t2;
            float2 p00 = __ldg(reinterpret_cast<const float2*>(tr0 + cb));
            float2 p10 = __ldg(reinterpret_cast<const float2*>(tr1 + cb));
            float2 p01 = __ldg(reinterpret_cast<const float2*>(tr0 + cb + 8));
            float2 p11 = __ldg(reinterpret_cast<const float2*>(tr1 + cb + 8));
            ea[mt][kt][0] = bpack(ex2(p00.x * L2E), ex2(p00.y * L2E));
            ea[mt][kt][1] = bpack(ex2(p10.x * L2E), ex2(p10.y * L2E));
            ea[mt][kt][2] = bpack(ex2(p01.x * L2E), ex2(p01.y * L2E));
            ea[mt][kt][3] = bpack(ex2(p11.x * L2E), ex2(p11.y * L2E));
        }
    }

    // ---- lengths: 16 threads per chain ----
    {
        int c = tid >> 4, j = tid & 15;
        const float* mr = mask + (size_t)(base + c) * S_;
        float lm = 0.f;
        for (int u = j; u < S_; u += 16) lm += mr[u];
#pragma unroll
        for (int o = 1; o < 16; o <<= 1) lm += __shfl_xor_sync(0xffffffffu, lm, o);
        if (j == 0) s_len[c] = (int)(lm + 0.5f);
    }
    // ---- init a0: 1 at START tag 0, else 0 ----
#pragma unroll
    for (int c = 0; c < NC; c++)
        sa[0][c][tid] = __float2bfloat16_rn(tid == 0 ? 1.f : 0.f);
    __syncthreads();

    const int len0 = s_len[c0], len1 = s_len[c1];
    int lenmax = s_len[0];
#pragma unroll
    for (int c = 1; c < NC; c++) lenmax = max(lenmax, s_len[c]);

    const float* xp0 = x + (size_t)(base + c0) * S_ * T_ + rA;
    const float* xp1 = x + (size_t)(base + c1) * S_ * T_ + rA;

    // x prefetch ring: exp2(x*log2e) for rows rA+{0,8,16,24} of both chains
    float xr[4][8];
#pragma unroll
    for (int d = 0; d < 4; d++) {
        const float* q0 = xp0 + (size_t)min(d, len0 - 1) * T_;
        const float* q1 = xp1 + (size_t)min(d, len1 - 1) * T_;
#pragma unroll
        for (int jj = 0; jj < 4; jj++) {
            xr[d][jj]     = ex2(__ldg(q0 + jj * 8) * L2E);
            xr[d][4 + jj] = ex2(__ldg(q1 + jj * 8) * L2E);
        }
    }

    int K0 = 0, K1 = 0;

#define STEP(PP, RD, TT)                                                     \
    {                                                                        \
        __syncthreads();                                                     \
        const bool act0_ = (TT) < len0, act1_ = (TT) < len1;                 \
        unsigned short h0_ =                                                 \
            *reinterpret_cast<const unsigned short*>(&sa[PP][c0][0]);        \
        unsigned short h1_ =                                                 \
            *reinterpret_cast<const unsigned short*>(&sa[PP][c1][0]);        \
        int k0_ = (int)((h0_ >> 7) & 255) - 127;                             \
        int k1_ = (int)((h1_ >> 7) & 255) - 127;                             \
        float s0_ = __int_as_float((127 - k0_) << 23);                       \
        float s1_ = __int_as_float((127 - k1_) << 23);                       \
        float d0a_[4] = {0.f,0.f,0.f,0.f}, d0b_[4] = {0.f,0.f,0.f,0.f};      \
        float d1a_[4] = {0.f,0.f,0.f,0.f}, d1b_[4] = {0.f,0.f,0.f,0.f};      \
        _Pragma("unroll")                                                    \
        for (int kt_ = 0; kt_ < 4; kt_++) {                                  \
            unsigned int b0_ = *reinterpret_cast<const unsigned int*>(       \
                &sa[PP][g][kt_ * 16 + t2]);                                  \
            unsigned int b1_ = *reinterpret_cast<const unsigned int*>(       \
                &sa[PP][g][kt_ * 16 + t2 + 8]);                              \
            MMA(d0a_, ea[0][kt_], b0_, b1_);                                 \
            MMA(d1a_, ea[1][kt_], b0_, b1_);                                 \
        }                                                                    \
        _Pragma("unroll")                                                    \
        for (int kt_ = 4; kt_ < 8; kt_++) {                                  \
            unsigned int b0_ = *reinterpret_cast<const unsigned int*>(       \
                &sa[PP][g][kt_ * 16 + t2]);                                  \
            unsigned int b1_ = *reinterpret_cast<const unsigned int*>(       \
                &sa[PP][g][kt_ * 16 + t2 + 8]);                              \
            MMA(d0b_, ea[0][kt_], b0_, b1_);                                 \
            MMA(d1b_, ea[1][kt_], b0_, b1_);                                 \
        }                                                                    \
        if (act0_) {                                                         \
            K0 += k0_;                                                       \
            float e0_ = xr[RD][0] * s0_, e1_ = xr[RD][1] * s0_;              \
            float e2_ = xr[RD][2] * s0_, e3_ = xr[RD][3] * s0_;              \
            sa[(PP)^1][c0][rA]      = __float2bfloat16_rn((d0a_[0]+d0b_[0])*e0_); \
            sa[(PP)^1][c0][rA + 8]  = __float2bfloat16_rn((d0a_[2]+d0b_[2])*e1_); \
            sa[(PP)^1][c0][rA + 16] = __float2bfloat16_rn((d1a_[0]+d1b_[0])*e2_); \
            sa[(PP)^1][c0][rA + 24] = __float2bfloat16_rn((d1a_[2]+d1b_[2])*e3_); \
        }                                                                    \
        if (act1_) {                                                         \
            K1 += k1_;                                                       \
            float e0_ = xr[RD][4] * s1_, e1_ = xr[RD][5] * s1_;              \
            float e2_ = xr[RD][6] * s1_, e3_ = xr[RD][7] * s1_;              \
            sa[(PP)^1][c1][rA]      = __float2bfloat16_rn((d0a_[1]+d0b_[1])*e0_); \
            sa[(PP)^1][c1][rA + 8]  = __float2bfloat16_rn((d0a_[3]+d0b_[3])*e1_); \
            sa[(PP)^1][c1][rA + 16] = __float2bfloat16_rn((d1a_[1]+d1b_[1])*e2_); \
            sa[(PP)^1][c1][rA + 24] = __float2bfloat16_rn((d1a_[3]+d1b_[3])*e3_); \
        }                                                                    \
        {                                                                    \
            const float* q0_ = xp0 + (size_t)min((TT) + 4, len0 - 1) * T_;   \
            const float* q1_ = xp1 + (size_t)min((TT) + 4, len1 - 1) * T_;   \
            _Pragma("unroll")                                                \
            for (int jj_ = 0; jj_ < 4; jj_++) {                              \
                xr[RD][jj_]     = ex2(__ldg(q0_ + jj_ * 8) * L2E);           \
                xr[RD][4 + jj_] = ex2(__ldg(q1_ + jj_ * 8) * L2E);           \
            }                                                                \
        }                                                                    \
    }

    int t = 0;
    const int lf = lenmax & ~3;
    for (; t < lf; t += 4) {
        STEP(0, 0, t)
        STEP(1, 1, t + 1)
        STEP(0, 2, t + 2)
        STEP(1, 3, t + 3)
    }
    if (t < lenmax) { STEP(0, 0, t) t++; }
    if (t < lenmax) { STEP(1, 1, t) t++; }
    if (t < lenmax) { STEP(0, 2, t) t++; }
#undef STEP

    // ---- publish per-chain renorm K (threads 0..3 own chains 2i, 2i+1) ----
    __syncthreads();
    if (tid < 4) { s_K[2 * tid] = K0; s_K[2 * tid + 1] = K1; }
    __syncthreads();

    // ---- per-chain epilogue: fwd + gold (16 threads per chain) ----
    {
        int c = tid >> 4, j = tid & 15;
        int lc = s_len[c], bf = lc & 1;
        float part = 0.f;
#pragma unroll
        for (int jj = 0; jj < 8; jj++) {
            int tg = j + jj * 16;
            part += __bfloat162float(sa[bf][c][tg]) *
                    ex2(__ldg(trans + END_ID * T_ + tg) * L2E);
        }
#pragma unroll
        for (int o = 1; o < 16; o <<= 1)
            part += __shfl_xor_sync(0xffffffffu, part, o);

        const int* tb = tags + (size_t)(base + c) * S_;
        const float* xc = x + (size_t)(base + c) * S_ * T_;
        float gs = 0.f;
        for (int u = j; u < lc; u += 16) {
            int tn = tb[u + 1];
            gs += xc[(size_t)u * T_ + tn] + __ldg(trans + tn * T_ + tb[u]);
        }
#pragma unroll
        for (int o = 1; o < 16; o <<= 1)
            gs += __shfl_xor_sync(0xffffffffu, gs, o);

        if (j == 0) {
            float fwd = (lg2(part) + (float)s_K[c]) * LN2;
            gs += __ldg(trans + END_ID * T_ + tb[lc]);
            g_diff[base + c] = fwd - gs;
        }
    }

    // ---- fused finalize: last CTA computes the mean, resets counter ----
    if (tid == 0) {
        __threadfence();
        int vd = atomicAdd(&g_done, 1);
        s_last = (vd == NCTA - 1);
    }
    __syncthreads();
    if (s_last) {
        __threadfence();
        float ts = g_diff[tid]       + g_diff[tid + 128]
                 + g_diff[tid + 256] + g_diff[tid + 384];
        ts = warp_sum(ts);
        __syncthreads();
        if (lane == 0) s_red[w] = ts;
        __syncthreads();
        if (tid == 0) {
            out[0] = (s_red[0] + s_red[1] + s_red[2] + s_red[3]) * (1.0f / B_);
            g_done = 0;   // reset for next graph replay
        }
    }
}

extern "C" void kernel_launch(void* const* d_in, const int* in_sizes, int n_in,
                              void* d_out, int out_size) {
    const float* x     = (const float*)d_in[0];
    const int*   tags  = (const int*)d_in[1];
    const float* mask  = (const float*)d_in[2];
    const float* trans = (const float*)d_in[3];
    crf_kernel<<<NCTA, 128>>>(x, tags, mask, trans, (float*)d_out);
}